// round 2
// baseline (speedup 1.0000x reference)
#include <cuda_runtime.h>
#include <math.h>

// Problem constants
#define BATCH 2
#define CH    512
#define NSP   4096          // 16*16*16 spatial
#define C3    1536          // 3*CH
#define NGRP  32
#define CPG   16            // channels per group
#define GSIZE (CPG*NSP)     // 65536 elements per group

// ---------------- scratch (device globals; no allocs allowed) ----------------
__device__ float g_seq  [(size_t)BATCH * NSP * CH];    // normalized, [b, n, c]
__device__ float g_qkv  [(size_t)BATCH * NSP * C3];    // [b, n, 3c]
__device__ float g_scor [(size_t)BATCH * NSP * NSP];   // [b, n, n]
__device__ float g_attn [(size_t)BATCH * NSP * CH];    // attn @ V, [b, n, c]
__device__ float g_proj [(size_t)BATCH * NSP * CH];    // proj output, [b, n, c]
__device__ float g_stats[BATCH * NGRP * 2];            // mean, rstd per (b,g)

// ---------------- reductions ----------------
__inline__ __device__ float warpSum(float v) {
    #pragma unroll
    for (int o = 16; o > 0; o >>= 1) v += __shfl_xor_sync(0xffffffffu, v, o);
    return v;
}
__inline__ __device__ float warpMax(float v) {
    #pragma unroll
    for (int o = 16; o > 0; o >>= 1) v = fmaxf(v, __shfl_xor_sync(0xffffffffu, v, o));
    return v;
}

// ---------------- GroupNorm stats: one block per (b,g) ----------------
__global__ void gn_stats_kernel(const float* __restrict__ x, float* __restrict__ stats) {
    int bg = blockIdx.x;                      // b*NGRP + g ; group region is contiguous
    const float* p = x + (size_t)bg * GSIZE;
    float s = 0.f, ss = 0.f;
    for (int i = threadIdx.x; i < GSIZE; i += 256) {
        float v = p[i];
        s += v; ss += v * v;
    }
    s = warpSum(s); ss = warpSum(ss);
    __shared__ float shs[8], shss[8];
    int w = threadIdx.x >> 5, l = threadIdx.x & 31;
    if (l == 0) { shs[w] = s; shss[w] = ss; }
    __syncthreads();
    if (threadIdx.x == 0) {
        float S = 0.f, SS = 0.f;
        #pragma unroll
        for (int i = 0; i < 8; i++) { S += shs[i]; SS += shss[i]; }
        float mean = S * (1.f / GSIZE);
        float var  = SS * (1.f / GSIZE) - mean * mean;
        stats[2 * bg]     = mean;
        stats[2 * bg + 1] = rsqrtf(var + 1e-6f);
    }
}

// ---------------- GroupNorm apply + transpose to [b, n, c] ----------------
// grid (NSP/32, CH/32, BATCH), block (32, 8)
__global__ void gn_apply_kernel(const float* __restrict__ x,
                                const float* __restrict__ stats,
                                const float* __restrict__ gw,
                                const float* __restrict__ gb,
                                float* __restrict__ seq) {
    __shared__ float t[32][33];
    int n0 = blockIdx.x * 32, c0 = blockIdx.y * 32, b = blockIdx.z;
    int tx = threadIdx.x, ty = threadIdx.y;
    #pragma unroll
    for (int j = 0; j < 4; j++) {
        int c = c0 + ty + j * 8;
        int bg = b * NGRP + (c >> 4);
        float mean = stats[2 * bg], rstd = stats[2 * bg + 1];
        float wv = gw[c] * rstd;
        float bv = gb[c] - mean * wv;
        float v = x[((size_t)(b * CH + c)) * NSP + n0 + tx];
        t[ty + j * 8][tx] = v * wv + bv;      // t[c_local][n_local]
    }
    __syncthreads();
    #pragma unroll
    for (int j = 0; j < 4; j++) {
        int n = n0 + ty + j * 8;
        seq[((size_t)(b * NSP + n)) * CH + c0 + tx] = t[tx][ty + j * 8];
    }
}

// ---------------- Tiled fp32 GEMM ----------------
// C[m][n] = alpha * sum_k A[m][k] * B'[k][n]  (+ bias[n])
// BT=true : B stored [N,K] row-major (NT gemm, B' = B^T)
// BT=false: B stored [K,N] row-major (NN gemm)
// BM=BN=128, BK=16, 256 threads, 8x8 per thread. All dims assumed multiples.
template <bool BT, bool BIAS>
__global__ void __launch_bounds__(256) gemm_kernel(
    const float* __restrict__ A, int lda, long long sA,
    const float* __restrict__ B, int ldb, long long sB,
    float* __restrict__ C, int ldc, long long sC,
    int K, float alpha, const float* __restrict__ bias) {

    __shared__ float As[16][128];
    __shared__ float Bs[16][128];

    A += blockIdx.z * sA + (long long)blockIdx.y * 128 * lda;
    B += blockIdx.z * sB;
    if (BT) B += (long long)blockIdx.x * 128 * ldb;
    else    B += blockIdx.x * 128;
    C += blockIdx.z * sC + (long long)blockIdx.y * 128 * ldc + blockIdx.x * 128;

    const int tid = threadIdx.x;
    const int tr = tid >> 4;        // 0..15
    const int tc = tid & 15;        // 0..15

    // A/NT-B load mapping: 128 rows x 16 cols, float4
    const int arow = tid >> 2;          // 0..63
    const int acol = (tid & 3) * 4;     // 0,4,8,12
    // NN-B load mapping: 16 rows x 128 cols, float4
    const int brow = tid >> 5;          // 0..7
    const int bcol = (tid & 31) * 4;    // 0..124

    float acc[8][8];
    #pragma unroll
    for (int i = 0; i < 8; i++)
        #pragma unroll
        for (int j = 0; j < 8; j++) acc[i][j] = 0.f;

    for (int k0 = 0; k0 < K; k0 += 16) {
        #pragma unroll
        for (int r = 0; r < 2; r++) {
            float4 v = *(const float4*)(A + (long long)(arow + 64 * r) * lda + k0 + acol);
            As[acol + 0][arow + 64 * r] = v.x;
            As[acol + 1][arow + 64 * r] = v.y;
            As[acol + 2][arow + 64 * r] = v.z;
            As[acol + 3][arow + 64 * r] = v.w;
        }
        if (BT) {
            #pragma unroll
            for (int r = 0; r < 2; r++) {
                float4 v = *(const float4*)(B + (long long)(arow + 64 * r) * ldb + k0 + acol);
                Bs[acol + 0][arow + 64 * r] = v.x;
                Bs[acol + 1][arow + 64 * r] = v.y;
                Bs[acol + 2][arow + 64 * r] = v.z;
                Bs[acol + 3][arow + 64 * r] = v.w;
            }
        } else {
            #pragma unroll
            for (int r = 0; r < 2; r++) {
                float4 v = *(const float4*)(B + (long long)(k0 + brow + 8 * r) * ldb + bcol);
                *(float4*)&Bs[brow + 8 * r][bcol] = v;
            }
        }
        __syncthreads();

        #pragma unroll
        for (int kk = 0; kk < 16; kk++) {
            float ra[8], rb[8];
            *(float4*)(ra)     = *(const float4*)&As[kk][tr * 8];
            *(float4*)(ra + 4) = *(const float4*)&As[kk][tr * 8 + 4];
            *(float4*)(rb)     = *(const float4*)&Bs[kk][tc * 8];
            *(float4*)(rb + 4) = *(const float4*)&Bs[kk][tc * 8 + 4];
            #pragma unroll
            for (int i = 0; i < 8; i++)
                #pragma unroll
                for (int j = 0; j < 8; j++)
                    acc[i][j] += ra[i] * rb[j];
        }
        __syncthreads();
    }

    const float* bptr = BIAS ? (bias + blockIdx.x * 128) : nullptr;
    #pragma unroll
    for (int i = 0; i < 8; i++) {
        float* crow = C + (long long)(tr * 8 + i) * ldc + tc * 8;
        #pragma unroll
        for (int j4 = 0; j4 < 2; j4++) {
            float4 v;
            v.x = alpha * acc[i][j4 * 4 + 0];
            v.y = alpha * acc[i][j4 * 4 + 1];
            v.z = alpha * acc[i][j4 * 4 + 2];
            v.w = alpha * acc[i][j4 * 4 + 3];
            if (BIAS) {
                v.x += bptr[tc * 8 + j4 * 4 + 0];
                v.y += bptr[tc * 8 + j4 * 4 + 1];
                v.z += bptr[tc * 8 + j4 * 4 + 2];
                v.w += bptr[tc * 8 + j4 * 4 + 3];
            }
            *(float4*)(crow + j4 * 4) = v;
        }
    }
}

// ---------------- row softmax over 4096, one block per row ----------------
__global__ void __launch_bounds__(256) softmax_kernel(float* __restrict__ S) {
    float* p = S + (size_t)blockIdx.x * NSP;
    float4 v[4];
    const int t = threadIdx.x;
    float m = -1e30f;
    #pragma unroll
    for (int i = 0; i < 4; i++) {
        v[i] = ((const float4*)p)[t + 256 * i];
        m = fmaxf(m, fmaxf(fmaxf(v[i].x, v[i].y), fmaxf(v[i].z, v[i].w)));
    }
    __shared__ float red[8];
    int w = t >> 5, l = t & 31;
    m = warpMax(m);
    if (l == 0) red[w] = m;
    __syncthreads();
    if (w == 0) {
        float tm = (l < 8) ? red[l] : -1e30f;
        tm = warpMax(tm);
        if (l == 0) red[0] = tm;
    }
    __syncthreads();
    m = red[0];
    __syncthreads();

    float s = 0.f;
    #pragma unroll
    for (int i = 0; i < 4; i++) {
        v[i].x = __expf(v[i].x - m);
        v[i].y = __expf(v[i].y - m);
        v[i].z = __expf(v[i].z - m);
        v[i].w = __expf(v[i].w - m);
        s += v[i].x + v[i].y + v[i].z + v[i].w;
    }
    s = warpSum(s);
    if (l == 0) red[w] = s;
    __syncthreads();
    if (w == 0) {
        float ts = (l < 8) ? red[l] : 0.f;
        ts = warpSum(ts);
        if (l == 0) red[0] = ts;
    }
    __syncthreads();
    float inv = __frcp_rn(red[0]);
    #pragma unroll
    for (int i = 0; i < 4; i++) {
        v[i].x *= inv; v[i].y *= inv; v[i].z *= inv; v[i].w *= inv;
        ((float4*)p)[t + 256 * i] = v[i];
    }
}

// ---------------- residual + transpose back to [b, c, n] ----------------
// grid (NSP/32, CH/32, BATCH), block (32, 8)
__global__ void residual_kernel(const float* __restrict__ x,
                                const float* __restrict__ proj,
                                float* __restrict__ out) {
    __shared__ float t[32][33];
    int n0 = blockIdx.x * 32, c0 = blockIdx.y * 32, b = blockIdx.z;
    int tx = threadIdx.x, ty = threadIdx.y;
    #pragma unroll
    for (int j = 0; j < 4; j++) {
        int n = n0 + ty + j * 8;
        t[ty + j * 8][tx] = proj[((size_t)(b * NSP + n)) * CH + c0 + tx];  // t[n_local][c_local]
    }
    __syncthreads();
    #pragma unroll
    for (int j = 0; j < 4; j++) {
        int c = c0 + ty + j * 8;
        size_t oi = ((size_t)(b * CH + c)) * NSP + n0 + tx;
        out[oi] = x[oi] + t[tx][ty + j * 8];
    }
}

// ---------------- launch ----------------
extern "C" void kernel_launch(void* const* d_in, const int* in_sizes, int n_in,
                              void* d_out, int out_size) {
    const float* x     = (const float*)d_in[0];
    const float* gw    = (const float*)d_in[1];
    const float* gb    = (const float*)d_in[2];
    const float* qkvW  = (const float*)d_in[3];
    const float* qkvB  = (const float*)d_in[4];
    const float* projW = (const float*)d_in[5];
    const float* projB = (const float*)d_in[6];
    float* out = (float*)d_out;

    float *seq, *qkv, *scor, *attn, *proj, *stats;
    cudaGetSymbolAddress((void**)&seq,   g_seq);
    cudaGetSymbolAddress((void**)&qkv,   g_qkv);
    cudaGetSymbolAddress((void**)&scor,  g_scor);
    cudaGetSymbolAddress((void**)&attn,  g_attn);
    cudaGetSymbolAddress((void**)&proj,  g_proj);
    cudaGetSymbolAddress((void**)&stats, g_stats);

    // 1. GroupNorm
    gn_stats_kernel<<<BATCH * NGRP, 256>>>(x, stats);
    gn_apply_kernel<<<dim3(NSP / 32, CH / 32, BATCH), dim3(32, 8)>>>(x, stats, gw, gb, seq);

    // 2. QKV projection: [8192,512] x [1536,512]^T -> [8192,1536]
    gemm_kernel<true, true><<<dim3(C3 / 128, (BATCH * NSP) / 128, 1), 256>>>(
        seq, CH, 0, qkvW, CH, 0, qkv, C3, 0, CH, 1.f, qkvB);

    // 3. Scores: Q K^T * scale (batched)
    const float scale = 0.044194173824159216f;  // 512^-0.5
    gemm_kernel<true, false><<<dim3(NSP / 128, NSP / 128, BATCH), 256>>>(
        qkv, C3, (long long)NSP * C3,
        qkv + CH, C3, (long long)NSP * C3,
        scor, NSP, (long long)NSP * NSP,
        CH, scale, nullptr);

    // 4. Softmax over rows
    softmax_kernel<<<BATCH * NSP, 256>>>(scor);

    // 5. O = P V (NN gemm, batched)
    gemm_kernel<false, false><<<dim3(CH / 128, NSP / 128, BATCH), 256>>>(
        scor, NSP, (long long)NSP * NSP,
        qkv + 2 * CH, C3, (long long)NSP * C3,
        attn, CH, (long long)NSP * CH,
        NSP, 1.f, nullptr);

    // 6. Output projection
    gemm_kernel<true, true><<<dim3(CH / 128, (BATCH * NSP) / 128, 1), 256>>>(
        attn, CH, 0, projW, CH, 0, proj, CH, 0, CH, 1.f, projB);

    // 7. Residual + transpose back to [b, c, h, w, d]
    residual_kernel<<<dim3(NSP / 32, CH / 32, BATCH), dim3(32, 8)>>>(x, proj, out);
}

// round 3
// speedup vs baseline: 3.0357x; 3.0357x over previous
#include <cuda_runtime.h>
#include <math.h>
#include <stdint.h>

// Problem constants
#define BATCH 2
#define CH    512
#define NSP   4096          // 16*16*16 spatial
#define C3    1536          // 3*CH
#define NGRP  32
#define CPG   16            // channels per group
#define GSIZE (CPG*NSP)     // 65536 elements per group

// ---------------- scratch (device globals; no allocs allowed) ----------------
__device__ float g_seq  [(size_t)BATCH * NSP * CH];    // normalized, [b, n, c]
__device__ float g_qkv  [(size_t)BATCH * NSP * C3];    // [b, n, 3c]
__device__ float g_scor [(size_t)BATCH * NSP * NSP];   // [b, n, n]
__device__ float g_attn [(size_t)BATCH * NSP * CH];    // attn @ V, [b, n, c]
__device__ float g_proj [(size_t)BATCH * NSP * CH];    // proj output, [b, n, c]
__device__ float g_stats[BATCH * NGRP * 2];            // mean, rstd per (b,g)

// ---------------- reductions ----------------
__inline__ __device__ float warpSum(float v) {
    #pragma unroll
    for (int o = 16; o > 0; o >>= 1) v += __shfl_xor_sync(0xffffffffu, v, o);
    return v;
}
__inline__ __device__ float warpMax(float v) {
    #pragma unroll
    for (int o = 16; o > 0; o >>= 1) v = fmaxf(v, __shfl_xor_sync(0xffffffffu, v, o));
    return v;
}

__inline__ __device__ float to_tf32(float x) {
    uint32_t u;
    asm("cvt.rna.tf32.f32 %0, %1;" : "=r"(u) : "f"(x));
    return __uint_as_float(u);
}

// ---------------- GroupNorm stats: one block per (b,g) ----------------
__global__ void gn_stats_kernel(const float* __restrict__ x, float* __restrict__ stats) {
    int bg = blockIdx.x;
    const float* p = x + (size_t)bg * GSIZE;
    float s = 0.f, ss = 0.f;
    for (int i = threadIdx.x; i < GSIZE; i += 256) {
        float v = p[i];
        s += v; ss += v * v;
    }
    s = warpSum(s); ss = warpSum(ss);
    __shared__ float shs[8], shss[8];
    int w = threadIdx.x >> 5, l = threadIdx.x & 31;
    if (l == 0) { shs[w] = s; shss[w] = ss; }
    __syncthreads();
    if (threadIdx.x == 0) {
        float S = 0.f, SS = 0.f;
        #pragma unroll
        for (int i = 0; i < 8; i++) { S += shs[i]; SS += shss[i]; }
        float mean = S * (1.f / GSIZE);
        float var  = SS * (1.f / GSIZE) - mean * mean;
        stats[2 * bg]     = mean;
        stats[2 * bg + 1] = rsqrtf(var + 1e-6f);
    }
}

// ---------------- GroupNorm apply + transpose to [b, n, c] ----------------
__global__ void gn_apply_kernel(const float* __restrict__ x,
                                const float* __restrict__ stats,
                                const float* __restrict__ gw,
                                const float* __restrict__ gb,
                                float* __restrict__ seq) {
    __shared__ float t[32][33];
    int n0 = blockIdx.x * 32, c0 = blockIdx.y * 32, b = blockIdx.z;
    int tx = threadIdx.x, ty = threadIdx.y;
    #pragma unroll
    for (int j = 0; j < 4; j++) {
        int c = c0 + ty + j * 8;
        int bg = b * NGRP + (c >> 4);
        float mean = stats[2 * bg], rstd = stats[2 * bg + 1];
        float wv = gw[c] * rstd;
        float bv = gb[c] - mean * wv;
        float v = x[((size_t)(b * CH + c)) * NSP + n0 + tx];
        t[ty + j * 8][tx] = v * wv + bv;
    }
    __syncthreads();
    #pragma unroll
    for (int j = 0; j < 4; j++) {
        int n = n0 + ty + j * 8;
        seq[((size_t)(b * NSP + n)) * CH + c0 + tx] = t[tx][ty + j * 8];
    }
}

// ---------------- tf32 mma.sync GEMM ----------------
// C[m][n] = alpha * sum_k A[m][k] * B'[k][n]  (+ bias[n])
// BT=true : B stored [N,K] row-major (NT gemm)
// BT=false: B stored [K,N] row-major (NN gemm)
// BM=BN=128, BK=32, 256 threads (8 warps as 2x4), warp tile 64x32,
// fragments m16n8k8 tf32. Double-buffered dynamic smem.
#define BKP 36            // padded A/B(NT) k-stride -> conflict-free frag lds
#define BNP 136           // padded B(NN) n-stride  -> conflict-free frag lds

template <bool BT, bool BIAS>
__global__ void __launch_bounds__(256, 2) mma_gemm(
    const float* __restrict__ A, int lda, long long sA,
    const float* __restrict__ B, int ldb, long long sB,
    float* __restrict__ C, int ldc, long long sC,
    int K, float alpha, const float* __restrict__ bias) {

    extern __shared__ float sm[];
    float* As = sm;                       // [2][128*BKP]
    float* Bs = sm + 2 * 128 * BKP;       // [2][BSZ]
    constexpr int BSZ = BT ? 128 * BKP : 32 * BNP;

    A += blockIdx.z * sA + (long long)blockIdx.y * 128 * lda;
    if (BT) B += blockIdx.z * sB + (long long)blockIdx.x * 128 * ldb;
    else    B += blockIdx.z * sB + blockIdx.x * 128;
    C += blockIdx.z * sC + (long long)blockIdx.y * 128 * ldc + blockIdx.x * 128;

    const int tid  = threadIdx.x;
    const int lane = tid & 31;
    const int warpM = (tid >> 5) >> 2;   // 0..1
    const int warpN = (tid >> 5) & 3;    // 0..3
    const int g = lane >> 2, t4 = lane & 3;

    const int lrow = tid >> 3;           // 0..31
    const int lcol = (tid & 7) * 4;      // 0,4,...,28

    float acc[4][4][4];
    #pragma unroll
    for (int i = 0; i < 4; i++)
        #pragma unroll
        for (int j = 0; j < 4; j++)
            #pragma unroll
            for (int q = 0; q < 4; q++) acc[i][j][q] = 0.f;

    const int iters = K / 32;
    float4 av[4], bv[4];

    // prologue load (k0 = 0)
    #pragma unroll
    for (int r = 0; r < 4; r++)
        av[r] = *(const float4*)(A + (long long)(lrow + 32 * r) * lda + lcol);
    if (BT) {
        #pragma unroll
        for (int r = 0; r < 4; r++)
            bv[r] = *(const float4*)(B + (long long)(lrow + 32 * r) * ldb + lcol);
    } else {
        #pragma unroll
        for (int j = 0; j < 4; j++)
            bv[j] = *(const float4*)(B + (long long)lrow * ldb + lcol + j * 32);
    }

    // prologue store -> buf 0
    {
        #pragma unroll
        for (int r = 0; r < 4; r++) {
            float* dst = As + (lrow + 32 * r) * BKP + lcol;
            dst[0] = to_tf32(av[r].x); dst[1] = to_tf32(av[r].y);
            dst[2] = to_tf32(av[r].z); dst[3] = to_tf32(av[r].w);
        }
        if (BT) {
            #pragma unroll
            for (int r = 0; r < 4; r++) {
                float* dst = Bs + (lrow + 32 * r) * BKP + lcol;
                dst[0] = to_tf32(bv[r].x); dst[1] = to_tf32(bv[r].y);
                dst[2] = to_tf32(bv[r].z); dst[3] = to_tf32(bv[r].w);
            }
        } else {
            #pragma unroll
            for (int j = 0; j < 4; j++) {
                float* dst = Bs + lrow * BNP + lcol + j * 32;
                dst[0] = to_tf32(bv[j].x); dst[1] = to_tf32(bv[j].y);
                dst[2] = to_tf32(bv[j].z); dst[3] = to_tf32(bv[j].w);
            }
        }
    }
    __syncthreads();

    int buf = 0;
    for (int it = 0; it < iters; ++it) {
        if (it + 1 < iters) {
            int k0 = (it + 1) * 32;
            #pragma unroll
            for (int r = 0; r < 4; r++)
                av[r] = *(const float4*)(A + (long long)(lrow + 32 * r) * lda + k0 + lcol);
            if (BT) {
                #pragma unroll
                for (int r = 0; r < 4; r++)
                    bv[r] = *(const float4*)(B + (long long)(lrow + 32 * r) * ldb + k0 + lcol);
            } else {
                #pragma unroll
                for (int j = 0; j < 4; j++)
                    bv[j] = *(const float4*)(B + (long long)(k0 + lrow) * ldb + lcol + j * 32);
            }
        }

        // compute from buf
        const float* Ab = As + buf * (128 * BKP);
        const float* Bb = Bs + buf * BSZ;
        #pragma unroll
        for (int kk = 0; kk < 4; kk++) {
            const int k = kk * 8;
            uint32_t af[4][4];
            #pragma unroll
            for (int mf = 0; mf < 4; mf++) {
                const int mb = warpM * 64 + mf * 16;
                af[mf][0] = __float_as_uint(Ab[(mb + g)     * BKP + k + t4]);
                af[mf][1] = __float_as_uint(Ab[(mb + g + 8) * BKP + k + t4]);
                af[mf][2] = __float_as_uint(Ab[(mb + g)     * BKP + k + t4 + 4]);
                af[mf][3] = __float_as_uint(Ab[(mb + g + 8) * BKP + k + t4 + 4]);
            }
            uint32_t bf[4][2];
            #pragma unroll
            for (int nf = 0; nf < 4; nf++) {
                const int nb = warpN * 32 + nf * 8;
                if (BT) {
                    bf[nf][0] = __float_as_uint(Bb[(nb + g) * BKP + k + t4]);
                    bf[nf][1] = __float_as_uint(Bb[(nb + g) * BKP + k + t4 + 4]);
                } else {
                    bf[nf][0] = __float_as_uint(Bb[(k + t4)     * BNP + nb + g]);
                    bf[nf][1] = __float_as_uint(Bb[(k + t4 + 4) * BNP + nb + g]);
                }
            }
            #pragma unroll
            for (int mf = 0; mf < 4; mf++)
                #pragma unroll
                for (int nf = 0; nf < 4; nf++) {
                    asm volatile(
                        "mma.sync.aligned.m16n8k8.row.col.f32.tf32.tf32.f32 "
                        "{%0,%1,%2,%3}, {%4,%5,%6,%7}, {%8,%9}, {%0,%1,%2,%3};"
                        : "+f"(acc[mf][nf][0]), "+f"(acc[mf][nf][1]),
                          "+f"(acc[mf][nf][2]), "+f"(acc[mf][nf][3])
                        : "r"(af[mf][0]), "r"(af[mf][1]), "r"(af[mf][2]), "r"(af[mf][3]),
                          "r"(bf[nf][0]), "r"(bf[nf][1]));
                }
        }
        __syncthreads();

        if (it + 1 < iters) {
            float* Aw = As + (buf ^ 1) * (128 * BKP);
            float* Bw = Bs + (buf ^ 1) * BSZ;
            #pragma unroll
            for (int r = 0; r < 4; r++) {
                float* dst = Aw + (lrow + 32 * r) * BKP + lcol;
                dst[0] = to_tf32(av[r].x); dst[1] = to_tf32(av[r].y);
                dst[2] = to_tf32(av[r].z); dst[3] = to_tf32(av[r].w);
            }
            if (BT) {
                #pragma unroll
                for (int r = 0; r < 4; r++) {
                    float* dst = Bw + (lrow + 32 * r) * BKP + lcol;
                    dst[0] = to_tf32(bv[r].x); dst[1] = to_tf32(bv[r].y);
                    dst[2] = to_tf32(bv[r].z); dst[3] = to_tf32(bv[r].w);
                }
            } else {
                #pragma unroll
                for (int j = 0; j < 4; j++) {
                    float* dst = Bw + lrow * BNP + lcol + j * 32;
                    dst[0] = to_tf32(bv[j].x); dst[1] = to_tf32(bv[j].y);
                    dst[2] = to_tf32(bv[j].z); dst[3] = to_tf32(bv[j].w);
                }
            }
            buf ^= 1;
            __syncthreads();
        }
    }

    // epilogue
    const float* bptr = BIAS ? (bias + blockIdx.x * 128) : nullptr;
    #pragma unroll
    for (int mf = 0; mf < 4; mf++) {
        const int row = warpM * 64 + mf * 16 + g;
        #pragma unroll
        for (int nf = 0; nf < 4; nf++) {
            const int col = warpN * 32 + nf * 8 + 2 * t4;
            float b0 = 0.f, b1 = 0.f;
            if (BIAS) { b0 = bptr[col]; b1 = bptr[col + 1]; }
            float2 v0 = { alpha * acc[mf][nf][0] + b0, alpha * acc[mf][nf][1] + b1 };
            float2 v1 = { alpha * acc[mf][nf][2] + b0, alpha * acc[mf][nf][3] + b1 };
            *(float2*)(C + (long long)row * ldc + col)       = v0;
            *(float2*)(C + (long long)(row + 8) * ldc + col) = v1;
        }
    }
}

#define MMA_SMEM 73728   // max over NT/NN instantiations

// ---------------- row softmax over 4096, one block per row ----------------
__global__ void __launch_bounds__(256) softmax_kernel(float* __restrict__ S) {
    float* p = S + (size_t)blockIdx.x * NSP;
    float4 v[4];
    const int t = threadIdx.x;
    float m = -1e30f;
    #pragma unroll
    for (int i = 0; i < 4; i++) {
        v[i] = ((const float4*)p)[t + 256 * i];
        m = fmaxf(m, fmaxf(fmaxf(v[i].x, v[i].y), fmaxf(v[i].z, v[i].w)));
    }
    __shared__ float red[8];
    int w = t >> 5, l = t & 31;
    m = warpMax(m);
    if (l == 0) red[w] = m;
    __syncthreads();
    if (w == 0) {
        float tm = (l < 8) ? red[l] : -1e30f;
        tm = warpMax(tm);
        if (l == 0) red[0] = tm;
    }
    __syncthreads();
    m = red[0];
    __syncthreads();

    float s = 0.f;
    #pragma unroll
    for (int i = 0; i < 4; i++) {
        v[i].x = __expf(v[i].x - m);
        v[i].y = __expf(v[i].y - m);
        v[i].z = __expf(v[i].z - m);
        v[i].w = __expf(v[i].w - m);
        s += v[i].x + v[i].y + v[i].z + v[i].w;
    }
    s = warpSum(s);
    if (l == 0) red[w] = s;
    __syncthreads();
    if (w == 0) {
        float ts = (l < 8) ? red[l] : 0.f;
        ts = warpSum(ts);
        if (l == 0) red[0] = ts;
    }
    __syncthreads();
    float inv = __frcp_rn(red[0]);
    #pragma unroll
    for (int i = 0; i < 4; i++) {
        v[i].x *= inv; v[i].y *= inv; v[i].z *= inv; v[i].w *= inv;
        ((float4*)p)[t + 256 * i] = v[i];
    }
}

// ---------------- residual + transpose back to [b, c, n] ----------------
__global__ void residual_kernel(const float* __restrict__ x,
                                const float* __restrict__ proj,
                                float* __restrict__ out) {
    __shared__ float t[32][33];
    int n0 = blockIdx.x * 32, c0 = blockIdx.y * 32, b = blockIdx.z;
    int tx = threadIdx.x, ty = threadIdx.y;
    #pragma unroll
    for (int j = 0; j < 4; j++) {
        int n = n0 + ty + j * 8;
        t[ty + j * 8][tx] = proj[((size_t)(b * NSP + n)) * CH + c0 + tx];
    }
    __syncthreads();
    #pragma unroll
    for (int j = 0; j < 4; j++) {
        int c = c0 + ty + j * 8;
        size_t oi = ((size_t)(b * CH + c)) * NSP + n0 + tx;
        out[oi] = x[oi] + t[tx][ty + j * 8];
    }
}

// ---------------- launch ----------------
extern "C" void kernel_launch(void* const* d_in, const int* in_sizes, int n_in,
                              void* d_out, int out_size) {
    const float* x     = (const float*)d_in[0];
    const float* gw    = (const float*)d_in[1];
    const float* gb    = (const float*)d_in[2];
    const float* qkvW  = (const float*)d_in[3];
    const float* qkvB  = (const float*)d_in[4];
    const float* projW = (const float*)d_in[5];
    const float* projB = (const float*)d_in[6];
    float* out = (float*)d_out;

    float *seq, *qkv, *scor, *attn, *proj, *stats;
    cudaGetSymbolAddress((void**)&seq,   g_seq);
    cudaGetSymbolAddress((void**)&qkv,   g_qkv);
    cudaGetSymbolAddress((void**)&scor,  g_scor);
    cudaGetSymbolAddress((void**)&attn,  g_attn);
    cudaGetSymbolAddress((void**)&proj,  g_proj);
    cudaGetSymbolAddress((void**)&stats, g_stats);

    static bool attr_done = false;
    if (!attr_done) {
        cudaFuncSetAttribute((const void*)mma_gemm<true, true>,
                             cudaFuncAttributeMaxDynamicSharedMemorySize, MMA_SMEM);
        cudaFuncSetAttribute((const void*)mma_gemm<true, false>,
                             cudaFuncAttributeMaxDynamicSharedMemorySize, MMA_SMEM);
        cudaFuncSetAttribute((const void*)mma_gemm<false, false>,
                             cudaFuncAttributeMaxDynamicSharedMemorySize, MMA_SMEM);
        attr_done = true;
    }

    // 1. GroupNorm
    gn_stats_kernel<<<BATCH * NGRP, 256>>>(x, stats);
    gn_apply_kernel<<<dim3(NSP / 32, CH / 32, BATCH), dim3(32, 8)>>>(x, stats, gw, gb, seq);

    // 2. QKV projection: [8192,512] x [1536,512]^T -> [8192,1536]
    mma_gemm<true, true><<<dim3(C3 / 128, (BATCH * NSP) / 128, 1), 256, MMA_SMEM>>>(
        seq, CH, 0, qkvW, CH, 0, qkv, C3, 0, CH, 1.f, qkvB);

    // 3. Scores: Q K^T * scale (batched)
    const float scale = 0.044194173824159216f;  // 512^-0.5
    mma_gemm<true, false><<<dim3(NSP / 128, NSP / 128, BATCH), 256, MMA_SMEM>>>(
        qkv, C3, (long long)NSP * C3,
        qkv + CH, C3, (long long)NSP * C3,
        scor, NSP, (long long)NSP * NSP,
        CH, scale, nullptr);

    // 4. Softmax over rows
    softmax_kernel<<<BATCH * NSP, 256>>>(scor);

    // 5. O = P V (NN gemm, batched)
    mma_gemm<false, false><<<dim3(CH / 128, NSP / 128, BATCH), 256, MMA_SMEM>>>(
        scor, NSP, (long long)NSP * NSP,
        qkv + 2 * CH, C3, (long long)NSP * C3,
        attn, CH, (long long)NSP * CH,
        NSP, 1.f, nullptr);

    // 6. Output projection
    mma_gemm<true, true><<<dim3(CH / 128, (BATCH * NSP) / 128, 1), 256, MMA_SMEM>>>(
        attn, CH, 0, projW, CH, 0, proj, CH, 0, CH, 1.f, projB);

    // 7. Residual + transpose back to [b, c, h, w, d]
    residual_kernel<<<dim3(NSP / 32, CH / 32, BATCH), dim3(32, 8)>>>(x, proj, out);
}

// round 5
// speedup vs baseline: 4.9288x; 1.6236x over previous
#include <cuda_runtime.h>
#include <cuda_fp16.h>
#include <math.h>
#include <stdint.h>

// Problem constants
#define BATCH 2
#define CH    512
#define NSP   4096
#define C3    1536
#define NGRP  32
#define GSIZE (16*NSP)

// ---------------- scratch ----------------
__device__ __half g_seqh [(size_t)BATCH * NSP * CH];
__device__ __half g_qkvh [(size_t)BATCH * NSP * C3];
__device__ __half g_ph   [(size_t)BATCH * NSP * NSP];
__device__ __half g_vth  [(size_t)BATCH * CH * NSP];
__device__ __half g_attnh[(size_t)BATCH * NSP * CH];
__device__ __half g_qkvWh[(size_t)C3 * CH];
__device__ __half g_projWh[(size_t)CH * CH];
__device__ float  g_scor [(size_t)BATCH * NSP * NSP];
__device__ float  g_proj [(size_t)BATCH * NSP * CH];
__device__ float  g_stats[BATCH * NGRP * 2];

// ---------------- helpers ----------------
__inline__ __device__ float warpSum(float v) {
    #pragma unroll
    for (int o = 16; o > 0; o >>= 1) v += __shfl_xor_sync(0xffffffffu, v, o);
    return v;
}
__inline__ __device__ float warpMax(float v) {
    #pragma unroll
    for (int o = 16; o > 0; o >>= 1) v = fmaxf(v, __shfl_xor_sync(0xffffffffu, v, o));
    return v;
}
__device__ __forceinline__ uint32_t smem_u32(const void* p) {
    uint32_t a;
    asm("{ .reg .u64 t; cvta.to.shared.u64 t, %1; cvt.u32.u64 %0, t; }" : "=r"(a) : "l"(p));
    return a;
}

// ---------------- GroupNorm stats ----------------
__global__ void gn_stats_kernel(const float* __restrict__ x, float* __restrict__ stats) {
    int bg = blockIdx.x;
    const float* p = x + (size_t)bg * GSIZE;
    float s = 0.f, ss = 0.f;
    for (int i = threadIdx.x; i < GSIZE; i += 256) {
        float v = p[i];
        s += v; ss += v * v;
    }
    s = warpSum(s); ss = warpSum(ss);
    __shared__ float shs[8], shss[8];
    int w = threadIdx.x >> 5, l = threadIdx.x & 31;
    if (l == 0) { shs[w] = s; shss[w] = ss; }
    __syncthreads();
    if (threadIdx.x == 0) {
        float S = 0.f, SS = 0.f;
        #pragma unroll
        for (int i = 0; i < 8; i++) { S += shs[i]; SS += shss[i]; }
        float mean = S * (1.f / GSIZE);
        float var  = SS * (1.f / GSIZE) - mean * mean;
        stats[2 * bg]     = mean;
        stats[2 * bg + 1] = rsqrtf(var + 1e-6f);
    }
}

// ---------------- GroupNorm apply + transpose -> half [b, n, c] ----------------
__global__ void gn_apply_kernel(const float* __restrict__ x,
                                const float* __restrict__ stats,
                                const float* __restrict__ gw,
                                const float* __restrict__ gb,
                                __half* __restrict__ seq) {
    __shared__ float t[32][33];
    int n0 = blockIdx.x * 32, c0 = blockIdx.y * 32, b = blockIdx.z;
    int tx = threadIdx.x, ty = threadIdx.y;
    #pragma unroll
    for (int j = 0; j < 4; j++) {
        int c = c0 + ty + j * 8;
        int bg = b * NGRP + (c >> 4);
        float mean = stats[2 * bg], rstd = stats[2 * bg + 1];
        float wv = gw[c] * rstd;
        float bv = gb[c] - mean * wv;
        float v = x[((size_t)(b * CH + c)) * NSP + n0 + tx];
        t[ty + j * 8][tx] = v * wv + bv;
    }
    __syncthreads();
    #pragma unroll
    for (int j = 0; j < 4; j++) {
        int n = n0 + ty + j * 8;
        seq[((size_t)(b * NSP + n)) * CH + c0 + tx] = __float2half(t[tx][ty + j * 8]);
    }
}

// ---------------- weight conversion fp32 -> fp16 ----------------
__global__ void wconv_kernel(const float* __restrict__ qkvW, const float* __restrict__ projW,
                             __half* __restrict__ qkvWh, __half* __restrict__ projWh) {
    int i = blockIdx.x * 256 + threadIdx.x;
    #pragma unroll
    for (int r = 0; r < 4; r++) {
        int idx = i * 4 + r;
        if (idx < C3 * CH) qkvWh[idx] = __float2half(qkvW[idx]);
        if (idx < CH * CH) projWh[idx] = __float2half(projW[idx]);
    }
}

// ---------------- V transpose: vth[b][c][n] = qkvh[b][n][2*CH + c] ----------------
__global__ void vtrans_kernel(const __half* __restrict__ qkv, __half* __restrict__ vt) {
    __shared__ __half t[32][33];
    int n0 = blockIdx.x * 32, c0 = blockIdx.y * 32, b = blockIdx.z;
    int tx = threadIdx.x, ty = threadIdx.y;
    #pragma unroll
    for (int j = 0; j < 4; j++) {
        int n = n0 + ty + j * 8;
        t[ty + j * 8][tx] = qkv[((size_t)(b * NSP + n)) * C3 + 2 * CH + c0 + tx];
    }
    __syncthreads();
    #pragma unroll
    for (int j = 0; j < 4; j++) {
        int c = c0 + ty + j * 8;
        vt[((size_t)(b * CH + c)) * NSP + n0 + tx] = t[tx][ty + j * 8];
    }
}

// ---------------- fp16 NT GEMM (mma.sync m16n8k16), cp.async 3-stage ----------------
// C[m][n] = alpha * sum_k A[m][k]*B[n][k] (+bias[n]); A,B half, C half or float.
// BM=BN=128, BK=32, 256 threads (2x4 warps), warp tile 64x32.
// smem row stride: 40 halfs (80B) -> conflict-free half2 frag loads.
#define HROW 40
#define STAGE_B 20480            // (128*40)*2B * 2 tiles
#define HG_SMEM (3 * STAGE_B)    // 61440

__device__ __forceinline__ void hfill(const __half* __restrict__ A,
                                      const __half* __restrict__ B,
                                      int lda, int ldb, int k0,
                                      uint32_t sbase, int stage, int tid) {
    uint32_t sa = sbase + stage * STAGE_B;
    uint32_t sb = sa + 10240;
    #pragma unroll
    for (int i = 0; i < 2; i++) {
        int idx = tid + 256 * i;
        int row = idx >> 2, c = idx & 3;
        const __half* g = A + (long long)row * lda + k0 + c * 8;
        asm volatile("cp.async.cg.shared.global [%0], [%1], 16;"
                     :: "r"(sa + row * 80 + c * 16), "l"(g));
    }
    #pragma unroll
    for (int i = 0; i < 2; i++) {
        int idx = tid + 256 * i;
        int row = idx >> 2, c = idx & 3;
        const __half* g = B + (long long)row * ldb + k0 + c * 8;
        asm volatile("cp.async.cg.shared.global [%0], [%1], 16;"
                     :: "r"(sb + row * 80 + c * 16), "l"(g));
    }
    asm volatile("cp.async.commit_group;" ::: "memory");
}

template <bool HOUT>
__global__ void __launch_bounds__(256, 2) hgemm(
    const __half* __restrict__ A, int lda, long long sA,
    const __half* __restrict__ B, int ldb, long long sB,
    void* __restrict__ Cv, int ldc, long long sC,
    int K, float alpha, const float* __restrict__ bias) {

    extern __shared__ char smem[];
    uint32_t sbase = smem_u32(smem);
    const __half* Sm = (const __half*)smem;

    const int tid = threadIdx.x;
    const int lane = tid & 31;
    const int wid = tid >> 5;
    const int warpM = wid >> 2;          // 0..1
    const int warpN = wid & 3;           // 0..3
    const int g = lane >> 2, t4 = lane & 3;

    A += blockIdx.z * sA + (long long)blockIdx.y * 128 * lda;
    B += blockIdx.z * sB + (long long)blockIdx.x * 128 * ldb;

    float acc[4][4][4];
    #pragma unroll
    for (int i = 0; i < 4; i++)
        #pragma unroll
        for (int j = 0; j < 4; j++)
            #pragma unroll
            for (int q = 0; q < 4; q++) acc[i][j][q] = 0.f;

    const int S = K / 32;

    hfill(A, B, lda, ldb, 0, sbase, 0, tid);
    hfill(A, B, lda, ldb, 32, sbase, 1, tid);

    #pragma unroll 1
    for (int s = 0; s < S; s++) {
        if (s + 1 < S) asm volatile("cp.async.wait_group 1;" ::: "memory");
        else           asm volatile("cp.async.wait_group 0;" ::: "memory");
        __syncthreads();
        if (s + 2 < S) hfill(A, B, lda, ldb, (s + 2) * 32, sbase, (s + 2) % 3, tid);

        const __half* Ab = Sm + (s % 3) * (STAGE_B / 2);
        const __half* Bb = Ab + 5120;

        #pragma unroll
        for (int kk = 0; kk < 2; kk++) {
            const int ko = kk * 16 + 2 * t4;
            uint32_t af[4][4];
            #pragma unroll
            for (int mf = 0; mf < 4; mf++) {
                const int mb = warpM * 64 + mf * 16;
                af[mf][0] = *(const uint32_t*)(Ab + (mb + g)     * HROW + ko);
                af[mf][1] = *(const uint32_t*)(Ab + (mb + g + 8) * HROW + ko);
                af[mf][2] = *(const uint32_t*)(Ab + (mb + g)     * HROW + ko + 8);
                af[mf][3] = *(const uint32_t*)(Ab + (mb + g + 8) * HROW + ko + 8);
            }
            uint32_t bf[4][2];
            #pragma unroll
            for (int nf = 0; nf < 4; nf++) {
                const int nb = warpN * 32 + nf * 8;
                bf[nf][0] = *(const uint32_t*)(Bb + (nb + g) * HROW + ko);
                bf[nf][1] = *(const uint32_t*)(Bb + (nb + g) * HROW + ko + 8);
            }
            #pragma unroll
            for (int mf = 0; mf < 4; mf++)
                #pragma unroll
                for (int nf = 0; nf < 4; nf++) {
                    asm volatile(
                        "mma.sync.aligned.m16n8k16.row.col.f32.f16.f16.f32 "
                        "{%0,%1,%2,%3}, {%4,%5,%6,%7}, {%8,%9}, {%0,%1,%2,%3};"
                        : "+f"(acc[mf][nf][0]), "+f"(acc[mf][nf][1]),
                          "+f"(acc[mf][nf][2]), "+f"(acc[mf][nf][3])
                        : "r"(af[mf][0]), "r"(af[mf][1]), "r"(af[mf][2]), "r"(af[mf][3]),
                          "r"(bf[nf][0]), "r"(bf[nf][1]));
                }
        }
        __syncthreads();
    }

    const float* bp = bias ? bias + blockIdx.x * 128 : nullptr;
    #pragma unroll
    for (int mf = 0; mf < 4; mf++) {
        const int row = warpM * 64 + mf * 16 + g;
        #pragma unroll
        for (int nf = 0; nf < 4; nf++) {
            const int col = warpN * 32 + nf * 8 + 2 * t4;
            float b0 = 0.f, b1 = 0.f;
            if (bp) { b0 = bp[col]; b1 = bp[col + 1]; }
            float v00 = alpha * acc[mf][nf][0] + b0;
            float v01 = alpha * acc[mf][nf][1] + b1;
            float v10 = alpha * acc[mf][nf][2] + b0;
            float v11 = alpha * acc[mf][nf][3] + b1;
            if (HOUT) {
                __half* C = (__half*)Cv + blockIdx.z * sC
                          + (long long)blockIdx.y * 128 * ldc + blockIdx.x * 128;
                *(__half2*)(C + (long long)row * ldc + col)       = __floats2half2_rn(v00, v01);
                *(__half2*)(C + (long long)(row + 8) * ldc + col) = __floats2half2_rn(v10, v11);
            } else {
                float* C = (float*)Cv + blockIdx.z * sC
                         + (long long)blockIdx.y * 128 * ldc + blockIdx.x * 128;
                float2 u0 = { v00, v01 }, u1 = { v10, v11 };
                *(float2*)(C + (long long)row * ldc + col)       = u0;
                *(float2*)(C + (long long)(row + 8) * ldc + col) = u1;
            }
        }
    }
}

// ---------------- row softmax fp32 -> half P ----------------
__global__ void __launch_bounds__(256) softmax_kernel(const float* __restrict__ S,
                                                      __half* __restrict__ P) {
    const float* p = S + (size_t)blockIdx.x * NSP;
    __half2* o = (__half2*)(P + (size_t)blockIdx.x * NSP);
    float4 v[4];
    const int t = threadIdx.x;
    float m = -1e30f;
    #pragma unroll
    for (int i = 0; i < 4; i++) {
        v[i] = ((const float4*)p)[t + 256 * i];
        m = fmaxf(m, fmaxf(fmaxf(v[i].x, v[i].y), fmaxf(v[i].z, v[i].w)));
    }
    __shared__ float red[8];
    int w = t >> 5, l = t & 31;
    m = warpMax(m);
    if (l == 0) red[w] = m;
    __syncthreads();
    if (w == 0) {
        float tm = (l < 8) ? red[l] : -1e30f;
        tm = warpMax(tm);
        if (l == 0) red[0] = tm;
    }
    __syncthreads();
    m = red[0];
    __syncthreads();

    float s = 0.f;
    #pragma unroll
    for (int i = 0; i < 4; i++) {
        v[i].x = __expf(v[i].x - m);
        v[i].y = __expf(v[i].y - m);
        v[i].z = __expf(v[i].z - m);
        v[i].w = __expf(v[i].w - m);
        s += v[i].x + v[i].y + v[i].z + v[i].w;
    }
    s = warpSum(s);
    if (l == 0) red[w] = s;
    __syncthreads();
    if (w == 0) {
        float ts = (l < 8) ? red[l] : 0.f;
        ts = warpSum(ts);
        if (l == 0) red[0] = ts;
    }
    __syncthreads();
    float inv = __frcp_rn(red[0]);
    #pragma unroll
    for (int i = 0; i < 4; i++) {
        int base = (t + 256 * i) * 2;
        o[base]     = __floats2half2_rn(v[i].x * inv, v[i].y * inv);
        o[base + 1] = __floats2half2_rn(v[i].z * inv, v[i].w * inv);
    }
}

// ---------------- residual + transpose back ----------------
__global__ void residual_kernel(const float* __restrict__ x,
                                const float* __restrict__ proj,
                                float* __restrict__ out) {
    __shared__ float t[32][33];
    int n0 = blockIdx.x * 32, c0 = blockIdx.y * 32, b = blockIdx.z;
    int tx = threadIdx.x, ty = threadIdx.y;
    #pragma unroll
    for (int j = 0; j < 4; j++) {
        int n = n0 + ty + j * 8;
        t[ty + j * 8][tx] = proj[((size_t)(b * NSP + n)) * CH + c0 + tx];
    }
    __syncthreads();
    #pragma unroll
    for (int j = 0; j < 4; j++) {
        int c = c0 + ty + j * 8;
        size_t oi = ((size_t)(b * CH + c)) * NSP + n0 + tx;
        out[oi] = x[oi] + t[tx][ty + j * 8];
    }
}

// ---------------- launch ----------------
extern "C" void kernel_launch(void* const* d_in, const int* in_sizes, int n_in,
                              void* d_out, int out_size) {
    const float* x     = (const float*)d_in[0];
    const float* gw    = (const float*)d_in[1];
    const float* gb    = (const float*)d_in[2];
    const float* qkvW  = (const float*)d_in[3];
    const float* qkvB  = (const float*)d_in[4];
    const float* projW = (const float*)d_in[5];
    const float* projB = (const float*)d_in[6];
    float* out = (float*)d_out;

    __half *seqh, *qkvh, *ph, *vth, *attnh, *qkvWh, *projWh;
    float *scor, *proj, *stats;
    cudaGetSymbolAddress((void**)&seqh,  g_seqh);
    cudaGetSymbolAddress((void**)&qkvh,  g_qkvh);
    cudaGetSymbolAddress((void**)&ph,    g_ph);
    cudaGetSymbolAddress((void**)&vth,   g_vth);
    cudaGetSymbolAddress((void**)&attnh, g_attnh);
    cudaGetSymbolAddress((void**)&qkvWh, g_qkvWh);
    cudaGetSymbolAddress((void**)&projWh,g_projWh);
    cudaGetSymbolAddress((void**)&scor,  g_scor);
    cudaGetSymbolAddress((void**)&proj,  g_proj);
    cudaGetSymbolAddress((void**)&stats, g_stats);

    static bool attr_done = false;
    if (!attr_done) {
        cudaFuncSetAttribute((const void*)hgemm<true>,
                             cudaFuncAttributeMaxDynamicSharedMemorySize, HG_SMEM);
        cudaFuncSetAttribute((const void*)hgemm<false>,
                             cudaFuncAttributeMaxDynamicSharedMemorySize, HG_SMEM);
        attr_done = true;
    }

    // 1. GroupNorm + weight conversion
    gn_stats_kernel<<<BATCH * NGRP, 256>>>(x, stats);
    wconv_kernel<<<C3 * CH / 1024, 256>>>(qkvW, projW, qkvWh, projWh);
    gn_apply_kernel<<<dim3(NSP / 32, CH / 32, BATCH), dim3(32, 8)>>>(x, stats, gw, gb, seqh);

    // 2. QKV projection: [8192,512]h x [1536,512]h^T -> half
    hgemm<true><<<dim3(C3 / 128, (BATCH * NSP) / 128, 1), 256, HG_SMEM>>>(
        seqh, CH, 0, qkvWh, CH, 0, qkvh, C3, 0, CH, 1.f, qkvB);

    // 3. V transpose
    vtrans_kernel<<<dim3(NSP / 32, CH / 32, BATCH), dim3(32, 8)>>>(qkvh, vth);

    // 4. Scores: Q K^T * scale -> fp32
    const float scale = 0.044194173824159216f;
    hgemm<false><<<dim3(NSP / 128, NSP / 128, BATCH), 256, HG_SMEM>>>(
        qkvh, C3, (long long)NSP * C3,
        qkvh + CH, C3, (long long)NSP * C3,
        scor, NSP, (long long)NSP * NSP,
        CH, scale, nullptr);

    // 5. Softmax -> half P
    softmax_kernel<<<BATCH * NSP, 256>>>(scor, ph);

    // 6. O = P V^T (NT, half out)
    hgemm<true><<<dim3(CH / 128, NSP / 128, BATCH), 256, HG_SMEM>>>(
        ph, NSP, (long long)NSP * NSP,
        vth, NSP, (long long)CH * NSP,
        attnh, CH, (long long)NSP * CH,
        NSP, 1.f, nullptr);

    // 7. Output projection -> fp32
    hgemm<false><<<dim3(CH / 128, (BATCH * NSP) / 128, 1), 256, HG_SMEM>>>(
        attnh, CH, 0, projWh, CH, 0, proj, CH, 0, CH, 1.f, projB);

    // 8. Residual + transpose back
    residual_kernel<<<dim3(NSP / 32, CH / 32, BATCH), dim3(32, 8)>>>(x, proj, out);
}

// round 6
// speedup vs baseline: 5.3879x; 1.0932x over previous
#include <cuda_runtime.h>
#include <cuda_fp16.h>
#include <math.h>
#include <stdint.h>

// Problem constants
#define BATCH 2
#define CH    512
#define NSP   4096
#define C3    1536
#define NGRP  32
#define GSIZE (16*NSP)

// ---------------- scratch ----------------
__device__ __half g_seqh [(size_t)BATCH * NSP * CH];
__device__ __half g_qkvh [(size_t)BATCH * NSP * C3];
__device__ __half g_ph   [(size_t)BATCH * NSP * NSP];
__device__ __half g_vth  [(size_t)BATCH * CH * NSP];
__device__ __half g_attnh[(size_t)BATCH * NSP * CH];
__device__ __half g_qkvWh[(size_t)C3 * CH];
__device__ __half g_projWh[(size_t)CH * CH];
__device__ float  g_scor [(size_t)BATCH * NSP * NSP];
__device__ float  g_proj [(size_t)BATCH * NSP * CH];
__device__ float  g_stats[BATCH * NGRP * 2];

// ---------------- helpers ----------------
__inline__ __device__ float warpSum(float v) {
    #pragma unroll
    for (int o = 16; o > 0; o >>= 1) v += __shfl_xor_sync(0xffffffffu, v, o);
    return v;
}
__inline__ __device__ float warpMax(float v) {
    #pragma unroll
    for (int o = 16; o > 0; o >>= 1) v = fmaxf(v, __shfl_xor_sync(0xffffffffu, v, o));
    return v;
}
__device__ __forceinline__ uint32_t smem_u32(const void* p) {
    uint32_t a;
    asm("{ .reg .u64 t; cvta.to.shared.u64 t, %1; cvt.u32.u64 %0, t; }" : "=r"(a) : "l"(p));
    return a;
}

// ---------------- GroupNorm stats ----------------
__global__ void gn_stats_kernel(const float* __restrict__ x, float* __restrict__ stats) {
    int bg = blockIdx.x;
    const float* p = x + (size_t)bg * GSIZE;
    float s = 0.f, ss = 0.f;
    for (int i = threadIdx.x; i < GSIZE; i += 256) {
        float v = p[i];
        s += v; ss += v * v;
    }
    s = warpSum(s); ss = warpSum(ss);
    __shared__ float shs[8], shss[8];
    int w = threadIdx.x >> 5, l = threadIdx.x & 31;
    if (l == 0) { shs[w] = s; shss[w] = ss; }
    __syncthreads();
    if (threadIdx.x == 0) {
        float S = 0.f, SS = 0.f;
        #pragma unroll
        for (int i = 0; i < 8; i++) { S += shs[i]; SS += shss[i]; }
        float mean = S * (1.f / GSIZE);
        float var  = SS * (1.f / GSIZE) - mean * mean;
        stats[2 * bg]     = mean;
        stats[2 * bg + 1] = rsqrtf(var + 1e-6f);
    }
}

// ---------------- GroupNorm apply + transpose -> half [b, n, c] ----------------
__global__ void gn_apply_kernel(const float* __restrict__ x,
                                const float* __restrict__ stats,
                                const float* __restrict__ gw,
                                const float* __restrict__ gb,
                                __half* __restrict__ seq) {
    __shared__ float t[32][33];
    int n0 = blockIdx.x * 32, c0 = blockIdx.y * 32, b = blockIdx.z;
    int tx = threadIdx.x, ty = threadIdx.y;
    #pragma unroll
    for (int j = 0; j < 4; j++) {
        int c = c0 + ty + j * 8;
        int bg = b * NGRP + (c >> 4);
        float mean = stats[2 * bg], rstd = stats[2 * bg + 1];
        float wv = gw[c] * rstd;
        float bv = gb[c] - mean * wv;
        float v = x[((size_t)(b * CH + c)) * NSP + n0 + tx];
        t[ty + j * 8][tx] = v * wv + bv;
    }
    __syncthreads();
    #pragma unroll
    for (int j = 0; j < 4; j++) {
        int n = n0 + ty + j * 8;
        seq[((size_t)(b * NSP + n)) * CH + c0 + tx] = __float2half(t[tx][ty + j * 8]);
    }
}

// ---------------- weight conversion fp32 -> fp16 ----------------
__global__ void wconv_kernel(const float* __restrict__ qkvW, const float* __restrict__ projW,
                             __half* __restrict__ qkvWh, __half* __restrict__ projWh) {
    int i = blockIdx.x * 256 + threadIdx.x;
    #pragma unroll
    for (int r = 0; r < 4; r++) {
        int idx = i * 4 + r;
        if (idx < C3 * CH) qkvWh[idx] = __float2half(qkvW[idx]);
        if (idx < CH * CH) projWh[idx] = __float2half(projW[idx]);
    }
}

// ---------------- V transpose ----------------
__global__ void vtrans_kernel(const __half* __restrict__ qkv, __half* __restrict__ vt) {
    __shared__ __half t[32][33];
    int n0 = blockIdx.x * 32, c0 = blockIdx.y * 32, b = blockIdx.z;
    int tx = threadIdx.x, ty = threadIdx.y;
    #pragma unroll
    for (int j = 0; j < 4; j++) {
        int n = n0 + ty + j * 8;
        t[ty + j * 8][tx] = qkv[((size_t)(b * NSP + n)) * C3 + 2 * CH + c0 + tx];
    }
    __syncthreads();
    #pragma unroll
    for (int j = 0; j < 4; j++) {
        int c = c0 + ty + j * 8;
        vt[((size_t)(b * CH + c)) * NSP + n0 + tx] = t[tx][ty + j * 8];
    }
}

// ---------------- fp16 NT GEMM: mma.sync m16n8k16 + ldmatrix, cp.async 3-stage ----
// BM=BN=128, BK=32, 256 threads (2x4 warps), warp tile 64x32.
// smem row stride 40 halfs (80B): ldmatrix phases conflict-free (bank-quad r*5 mod 8).
#define HROW 40
#define STAGE_B 20480
#define HG_SMEM (3 * STAGE_B)

__device__ __forceinline__ void hfill(const __half* __restrict__ A,
                                      const __half* __restrict__ B,
                                      int lda, int ldb, int k0,
                                      uint32_t sbase, int stage, int tid) {
    uint32_t sa = sbase + stage * STAGE_B;
    uint32_t sb = sa + 10240;
    #pragma unroll
    for (int i = 0; i < 2; i++) {
        int idx = tid + 256 * i;
        int row = idx >> 2, c = idx & 3;
        const __half* g = A + (long long)row * lda + k0 + c * 8;
        asm volatile("cp.async.cg.shared.global [%0], [%1], 16;"
                     :: "r"(sa + row * 80 + c * 16), "l"(g));
    }
    #pragma unroll
    for (int i = 0; i < 2; i++) {
        int idx = tid + 256 * i;
        int row = idx >> 2, c = idx & 3;
        const __half* g = B + (long long)row * ldb + k0 + c * 8;
        asm volatile("cp.async.cg.shared.global [%0], [%1], 16;"
                     :: "r"(sb + row * 80 + c * 16), "l"(g));
    }
    asm volatile("cp.async.commit_group;" ::: "memory");
}

template <bool HOUT>
__global__ void __launch_bounds__(256, 2) hgemm(
    const __half* __restrict__ A, int lda, long long sA,
    const __half* __restrict__ B, int ldb, long long sB,
    void* __restrict__ Cv, int ldc, long long sC,
    int K, float alpha, const float* __restrict__ bias) {

    extern __shared__ char smem[];
    uint32_t sbase = smem_u32(smem);

    const int tid = threadIdx.x;
    const int lane = tid & 31;
    const int wid = tid >> 5;
    const int warpM = wid >> 2;          // 0..1
    const int warpN = wid & 3;           // 0..3
    const int g = lane >> 2, t4 = lane & 3;
    const int l8 = lane & 7, lm = lane >> 3;   // ldmatrix lane decomposition

    A += blockIdx.z * sA + (long long)blockIdx.y * 128 * lda;
    B += blockIdx.z * sB + (long long)blockIdx.x * 128 * ldb;

    // ldmatrix per-thread byte offsets within a stage's A / B region.
    // A x4: matrices [r0-7,k0][r8-15,k0][r0-7,k8][r8-15,k8]
    const uint32_t a_off = (uint32_t)(((lm & 1) * 8 + l8) * 80 + (lm >> 1) * 16)
                         + (uint32_t)(warpM * 64) * 80;
    // B x4 (covers 2 n-frags): matrices [n0-7,k0][n0-7,k8][n8-15,k0][n8-15,k8]
    const uint32_t b_off = (uint32_t)(((lm >> 1) * 8 + l8) * 80 + (lm & 1) * 16)
                         + (uint32_t)(warpN * 32) * 80;

    float acc[4][4][4];
    #pragma unroll
    for (int i = 0; i < 4; i++)
        #pragma unroll
        for (int j = 0; j < 4; j++)
            #pragma unroll
            for (int q = 0; q < 4; q++) acc[i][j][q] = 0.f;

    const int S = K / 32;
    hfill(A, B, lda, ldb, 0, sbase, 0, tid);
    hfill(A, B, lda, ldb, 32, sbase, 1, tid);

    #pragma unroll 1
    for (int s = 0; s < S; s++) {
        if (s + 1 < S) asm volatile("cp.async.wait_group 1;" ::: "memory");
        else           asm volatile("cp.async.wait_group 0;" ::: "memory");
        __syncthreads();
        if (s + 2 < S) hfill(A, B, lda, ldb, (s + 2) * 32, sbase, (s + 2) % 3, tid);

        const uint32_t sAb = sbase + (s % 3) * STAGE_B;
        const uint32_t sBb = sAb + 10240;

        #pragma unroll
        for (int kk = 0; kk < 2; kk++) {
            const uint32_t kadd = kk * 32;
            uint32_t af[4][4];
            #pragma unroll
            for (int mf = 0; mf < 4; mf++) {
                asm volatile("ldmatrix.sync.aligned.m8n8.x4.shared.b16 {%0,%1,%2,%3}, [%4];"
                    : "=r"(af[mf][0]), "=r"(af[mf][1]), "=r"(af[mf][2]), "=r"(af[mf][3])
                    : "r"(sAb + a_off + mf * 1280 + kadd));
            }
            uint32_t bf[4][2];
            #pragma unroll
            for (int p = 0; p < 2; p++) {
                asm volatile("ldmatrix.sync.aligned.m8n8.x4.shared.b16 {%0,%1,%2,%3}, [%4];"
                    : "=r"(bf[2*p][0]), "=r"(bf[2*p][1]), "=r"(bf[2*p+1][0]), "=r"(bf[2*p+1][1])
                    : "r"(sBb + b_off + p * 1280 + kadd));
            }
            #pragma unroll
            for (int mf = 0; mf < 4; mf++)
                #pragma unroll
                for (int nf = 0; nf < 4; nf++) {
                    asm volatile(
                        "mma.sync.aligned.m16n8k16.row.col.f32.f16.f16.f32 "
                        "{%0,%1,%2,%3}, {%4,%5,%6,%7}, {%8,%9}, {%0,%1,%2,%3};"
                        : "+f"(acc[mf][nf][0]), "+f"(acc[mf][nf][1]),
                          "+f"(acc[mf][nf][2]), "+f"(acc[mf][nf][3])
                        : "r"(af[mf][0]), "r"(af[mf][1]), "r"(af[mf][2]), "r"(af[mf][3]),
                          "r"(bf[nf][0]), "r"(bf[nf][1]));
                }
        }
    }

    const float* bp = bias ? bias + blockIdx.x * 128 : nullptr;
    #pragma unroll
    for (int mf = 0; mf < 4; mf++) {
        const int row = warpM * 64 + mf * 16 + g;
        #pragma unroll
        for (int nf = 0; nf < 4; nf++) {
            const int col = warpN * 32 + nf * 8 + 2 * t4;
            float b0 = 0.f, b1 = 0.f;
            if (bp) { b0 = bp[col]; b1 = bp[col + 1]; }
            float v00 = alpha * acc[mf][nf][0] + b0;
            float v01 = alpha * acc[mf][nf][1] + b1;
            float v10 = alpha * acc[mf][nf][2] + b0;
            float v11 = alpha * acc[mf][nf][3] + b1;
            if (HOUT) {
                __half* C = (__half*)Cv + blockIdx.z * sC
                          + (long long)blockIdx.y * 128 * ldc + blockIdx.x * 128;
                *(__half2*)(C + (long long)row * ldc + col)       = __floats2half2_rn(v00, v01);
                *(__half2*)(C + (long long)(row + 8) * ldc + col) = __floats2half2_rn(v10, v11);
            } else {
                float* C = (float*)Cv + blockIdx.z * sC
                         + (long long)blockIdx.y * 128 * ldc + blockIdx.x * 128;
                float2 u0 = { v00, v01 }, u1 = { v10, v11 };
                *(float2*)(C + (long long)row * ldc + col)       = u0;
                *(float2*)(C + (long long)(row + 8) * ldc + col) = u1;
            }
        }
    }
}

// ---------------- row softmax fp32 -> half P ----------------
__global__ void __launch_bounds__(256) softmax_kernel(const float* __restrict__ S,
                                                      __half* __restrict__ P) {
    const float* p = S + (size_t)blockIdx.x * NSP;
    __half2* o = (__half2*)(P + (size_t)blockIdx.x * NSP);
    float4 v[4];
    const int t = threadIdx.x;
    float m = -1e30f;
    #pragma unroll
    for (int i = 0; i < 4; i++) {
        v[i] = ((const float4*)p)[t + 256 * i];
        m = fmaxf(m, fmaxf(fmaxf(v[i].x, v[i].y), fmaxf(v[i].z, v[i].w)));
    }
    __shared__ float red[8];
    int w = t >> 5, l = t & 31;
    m = warpMax(m);
    if (l == 0) red[w] = m;
    __syncthreads();
    if (w == 0) {
        float tm = (l < 8) ? red[l] : -1e30f;
        tm = warpMax(tm);
        if (l == 0) red[0] = tm;
    }
    __syncthreads();
    m = red[0];
    __syncthreads();

    float s = 0.f;
    #pragma unroll
    for (int i = 0; i < 4; i++) {
        v[i].x = __expf(v[i].x - m);
        v[i].y = __expf(v[i].y - m);
        v[i].z = __expf(v[i].z - m);
        v[i].w = __expf(v[i].w - m);
        s += v[i].x + v[i].y + v[i].z + v[i].w;
    }
    s = warpSum(s);
    if (l == 0) red[w] = s;
    __syncthreads();
    if (w == 0) {
        float ts = (l < 8) ? red[l] : 0.f;
        ts = warpSum(ts);
        if (l == 0) red[0] = ts;
    }
    __syncthreads();
    float inv = __frcp_rn(red[0]);
    #pragma unroll
    for (int i = 0; i < 4; i++) {
        int base = (t + 256 * i) * 2;
        o[base]     = __floats2half2_rn(v[i].x * inv, v[i].y * inv);
        o[base + 1] = __floats2half2_rn(v[i].z * inv, v[i].w * inv);
    }
}

// ---------------- residual + transpose back ----------------
__global__ void residual_kernel(const float* __restrict__ x,
                                const float* __restrict__ proj,
                                float* __restrict__ out) {
    __shared__ float t[32][33];
    int n0 = blockIdx.x * 32, c0 = blockIdx.y * 32, b = blockIdx.z;
    int tx = threadIdx.x, ty = threadIdx.y;
    #pragma unroll
    for (int j = 0; j < 4; j++) {
        int n = n0 + ty + j * 8;
        t[ty + j * 8][tx] = proj[((size_t)(b * NSP + n)) * CH + c0 + tx];
    }
    __syncthreads();
    #pragma unroll
    for (int j = 0; j < 4; j++) {
        int c = c0 + ty + j * 8;
        size_t oi = ((size_t)(b * CH + c)) * NSP + n0 + tx;
        out[oi] = x[oi] + t[tx][ty + j * 8];
    }
}

// ---------------- launch ----------------
extern "C" void kernel_launch(void* const* d_in, const int* in_sizes, int n_in,
                              void* d_out, int out_size) {
    const float* x     = (const float*)d_in[0];
    const float* gw    = (const float*)d_in[1];
    const float* gb    = (const float*)d_in[2];
    const float* qkvW  = (const float*)d_in[3];
    const float* qkvB  = (const float*)d_in[4];
    const float* projW = (const float*)d_in[5];
    const float* projB = (const float*)d_in[6];
    float* out = (float*)d_out;

    __half *seqh, *qkvh, *ph, *vth, *attnh, *qkvWh, *projWh;
    float *scor, *proj, *stats;
    cudaGetSymbolAddress((void**)&seqh,  g_seqh);
    cudaGetSymbolAddress((void**)&qkvh,  g_qkvh);
    cudaGetSymbolAddress((void**)&ph,    g_ph);
    cudaGetSymbolAddress((void**)&vth,   g_vth);
    cudaGetSymbolAddress((void**)&attnh, g_attnh);
    cudaGetSymbolAddress((void**)&qkvWh, g_qkvWh);
    cudaGetSymbolAddress((void**)&projWh,g_projWh);
    cudaGetSymbolAddress((void**)&scor,  g_scor);
    cudaGetSymbolAddress((void**)&proj,  g_proj);
    cudaGetSymbolAddress((void**)&stats, g_stats);

    static bool attr_done = false;
    if (!attr_done) {
        cudaFuncSetAttribute((const void*)hgemm<true>,
                             cudaFuncAttributeMaxDynamicSharedMemorySize, HG_SMEM);
        cudaFuncSetAttribute((const void*)hgemm<false>,
                             cudaFuncAttributeMaxDynamicSharedMemorySize, HG_SMEM);
        attr_done = true;
    }

    // 1. GroupNorm + weight conversion
    gn_stats_kernel<<<BATCH * NGRP, 256>>>(x, stats);
    wconv_kernel<<<C3 * CH / 1024, 256>>>(qkvW, projW, qkvWh, projWh);
    gn_apply_kernel<<<dim3(NSP / 32, CH / 32, BATCH), dim3(32, 8)>>>(x, stats, gw, gb, seqh);

    // 2. QKV projection
    hgemm<true><<<dim3(C3 / 128, (BATCH * NSP) / 128, 1), 256, HG_SMEM>>>(
        seqh, CH, 0, qkvWh, CH, 0, qkvh, C3, 0, CH, 1.f, qkvB);

    // 3. V transpose
    vtrans_kernel<<<dim3(NSP / 32, CH / 32, BATCH), dim3(32, 8)>>>(qkvh, vth);

    // 4. Scores: Q K^T * scale -> fp32
    const float scale = 0.044194173824159216f;
    hgemm<false><<<dim3(NSP / 128, NSP / 128, BATCH), 256, HG_SMEM>>>(
        qkvh, C3, (long long)NSP * C3,
        qkvh + CH, C3, (long long)NSP * C3,
        scor, NSP, (long long)NSP * NSP,
        CH, scale, nullptr);

    // 5. Softmax -> half P
    softmax_kernel<<<BATCH * NSP, 256>>>(scor, ph);

    // 6. O = P V^T
    hgemm<true><<<dim3(CH / 128, NSP / 128, BATCH), 256, HG_SMEM>>>(
        ph, NSP, (long long)NSP * NSP,
        vth, NSP, (long long)CH * NSP,
        attnh, CH, (long long)NSP * CH,
        NSP, 1.f, nullptr);

    // 7. Output projection -> fp32
    hgemm<false><<<dim3(CH / 128, (BATCH * NSP) / 128, 1), 256, HG_SMEM>>>(
        attnh, CH, 0, projWh, CH, 0, proj, CH, 0, CH, 1.f, projB);

    // 8. Residual + transpose back
    residual_kernel<<<dim3(NSP / 32, CH / 32, BATCH), dim3(32, 8)>>>(x, proj, out);
}

// round 7
// speedup vs baseline: 5.4675x; 1.0148x over previous
#include <cuda_runtime.h>
#include <cuda_fp16.h>
#include <math.h>
#include <stdint.h>

// Problem constants
#define BATCH 2
#define CH    512
#define NSP   4096
#define C3    1536
#define NGRP  32
#define GSIZE (16*NSP)

// ---------------- scratch ----------------
__device__ __half g_seqh [(size_t)BATCH * NSP * CH];
__device__ __half g_qkvh [(size_t)BATCH * NSP * C3];
__device__ __half g_ph   [(size_t)BATCH * NSP * NSP];
__device__ __half g_vth  [(size_t)BATCH * CH * NSP];
__device__ __half g_attnh[(size_t)BATCH * NSP * CH];
__device__ __half g_qkvWh[(size_t)C3 * CH];
__device__ __half g_projWh[(size_t)CH * CH];
__device__ float  g_scor [(size_t)BATCH * NSP * NSP];
__device__ float  g_proj [(size_t)BATCH * NSP * CH];
__device__ float  g_stats[BATCH * NGRP * 2];

// ---------------- helpers ----------------
__inline__ __device__ float warpSum(float v) {
    #pragma unroll
    for (int o = 16; o > 0; o >>= 1) v += __shfl_xor_sync(0xffffffffu, v, o);
    return v;
}
__inline__ __device__ float warpMax(float v) {
    #pragma unroll
    for (int o = 16; o > 0; o >>= 1) v = fmaxf(v, __shfl_xor_sync(0xffffffffu, v, o));
    return v;
}
__device__ __forceinline__ uint32_t smem_u32(const void* p) {
    uint32_t a;
    asm("{ .reg .u64 t; cvta.to.shared.u64 t, %1; cvt.u32.u64 %0, t; }" : "=r"(a) : "l"(p));
    return a;
}

// ---------------- GroupNorm stats ----------------
__global__ void gn_stats_kernel(const float* __restrict__ x, float* __restrict__ stats) {
    int bg = blockIdx.x;
    const float* p = x + (size_t)bg * GSIZE;
    float s = 0.f, ss = 0.f;
    for (int i = threadIdx.x; i < GSIZE; i += 256) {
        float v = p[i];
        s += v; ss += v * v;
    }
    s = warpSum(s); ss = warpSum(ss);
    __shared__ float shs[8], shss[8];
    int w = threadIdx.x >> 5, l = threadIdx.x & 31;
    if (l == 0) { shs[w] = s; shss[w] = ss; }
    __syncthreads();
    if (threadIdx.x == 0) {
        float S = 0.f, SS = 0.f;
        #pragma unroll
        for (int i = 0; i < 8; i++) { S += shs[i]; SS += shss[i]; }
        float mean = S * (1.f / GSIZE);
        float var  = SS * (1.f / GSIZE) - mean * mean;
        stats[2 * bg]     = mean;
        stats[2 * bg + 1] = rsqrtf(var + 1e-6f);
    }
}

// ---------------- GroupNorm apply + transpose -> half [b, n, c] ----------------
__global__ void gn_apply_kernel(const float* __restrict__ x,
                                const float* __restrict__ stats,
                                const float* __restrict__ gw,
                                const float* __restrict__ gb,
                                __half* __restrict__ seq) {
    __shared__ float t[32][33];
    int n0 = blockIdx.x * 32, c0 = blockIdx.y * 32, b = blockIdx.z;
    int tx = threadIdx.x, ty = threadIdx.y;
    #pragma unroll
    for (int j = 0; j < 4; j++) {
        int c = c0 + ty + j * 8;
        int bg = b * NGRP + (c >> 4);
        float mean = stats[2 * bg], rstd = stats[2 * bg + 1];
        float wv = gw[c] * rstd;
        float bv = gb[c] - mean * wv;
        float v = x[((size_t)(b * CH + c)) * NSP + n0 + tx];
        t[ty + j * 8][tx] = v * wv + bv;
    }
    __syncthreads();
    #pragma unroll
    for (int j = 0; j < 4; j++) {
        int n = n0 + ty + j * 8;
        seq[((size_t)(b * NSP + n)) * CH + c0 + tx] = __float2half(t[tx][ty + j * 8]);
    }
}

// ---------------- weight conversion fp32 -> fp16 ----------------
__global__ void wconv_kernel(const float* __restrict__ qkvW, const float* __restrict__ projW,
                             __half* __restrict__ qkvWh, __half* __restrict__ projWh) {
    int i = blockIdx.x * 256 + threadIdx.x;
    #pragma unroll
    for (int r = 0; r < 4; r++) {
        int idx = i * 4 + r;
        if (idx < C3 * CH) qkvWh[idx] = __float2half(qkvW[idx]);
        if (idx < CH * CH) projWh[idx] = __float2half(projW[idx]);
    }
}

// ---------------- V transpose ----------------
__global__ void vtrans_kernel(const __half* __restrict__ qkv, __half* __restrict__ vt) {
    __shared__ __half t[32][33];
    int n0 = blockIdx.x * 32, c0 = blockIdx.y * 32, b = blockIdx.z;
    int tx = threadIdx.x, ty = threadIdx.y;
    #pragma unroll
    for (int j = 0; j < 4; j++) {
        int n = n0 + ty + j * 8;
        t[ty + j * 8][tx] = qkv[((size_t)(b * NSP + n)) * C3 + 2 * CH + c0 + tx];
    }
    __syncthreads();
    #pragma unroll
    for (int j = 0; j < 4; j++) {
        int c = c0 + ty + j * 8;
        vt[((size_t)(b * CH + c)) * NSP + n0 + tx] = t[tx][ty + j * 8];
    }
}

// ---------------- fp16 NT GEMM: mma.sync m16n8k16 + ldmatrix, cp.async 5-stage ----
// BM=BN=128, BK=32, 256 threads (2x4 warps), warp tile 64x32.
// smem row stride 40 halfs (80B): ldmatrix phases conflict-free (bank-quad r*5 mod 8).
#define HROW 40
#define STAGE_B 20480
#define NSTAGE 5
#define HG_SMEM (NSTAGE * STAGE_B)   // 102400, 2 CTAs/SM -> 200KB

__device__ __forceinline__ void hfill(const __half* __restrict__ A,
                                      const __half* __restrict__ B,
                                      int lda, int ldb, int k0,
                                      uint32_t sbase, int stage, int tid) {
    uint32_t sa = sbase + stage * STAGE_B;
    uint32_t sb = sa + 10240;
    #pragma unroll
    for (int i = 0; i < 2; i++) {
        int idx = tid + 256 * i;
        int row = idx >> 2, c = idx & 3;
        const __half* g = A + (long long)row * lda + k0 + c * 8;
        asm volatile("cp.async.cg.shared.global [%0], [%1], 16;"
                     :: "r"(sa + row * 80 + c * 16), "l"(g));
    }
    #pragma unroll
    for (int i = 0; i < 2; i++) {
        int idx = tid + 256 * i;
        int row = idx >> 2, c = idx & 3;
        const __half* g = B + (long long)row * ldb + k0 + c * 8;
        asm volatile("cp.async.cg.shared.global [%0], [%1], 16;"
                     :: "r"(sb + row * 80 + c * 16), "l"(g));
    }
    asm volatile("cp.async.commit_group;" ::: "memory");
}

template <bool HOUT>
__global__ void __launch_bounds__(256, 2) hgemm(
    const __half* __restrict__ A, int lda, long long sA,
    const __half* __restrict__ B, int ldb, long long sB,
    void* __restrict__ Cv, int ldc, long long sC,
    int K, float alpha, const float* __restrict__ bias) {

    extern __shared__ char smem[];
    uint32_t sbase = smem_u32(smem);

    const int tid = threadIdx.x;
    const int lane = tid & 31;
    const int wid = tid >> 5;
    const int warpM = wid >> 2;          // 0..1
    const int warpN = wid & 3;           // 0..3
    const int g = lane >> 2, t4 = lane & 3;
    const int l8 = lane & 7, lm = lane >> 3;

    A += blockIdx.z * sA + (long long)blockIdx.y * 128 * lda;
    B += blockIdx.z * sB + (long long)blockIdx.x * 128 * ldb;

    // ldmatrix per-thread byte offsets within a stage's A / B region.
    const uint32_t a_off = (uint32_t)(((lm & 1) * 8 + l8) * 80 + (lm >> 1) * 16)
                         + (uint32_t)(warpM * 64) * 80;
    const uint32_t b_off = (uint32_t)(((lm >> 1) * 8 + l8) * 80 + (lm & 1) * 16)
                         + (uint32_t)(warpN * 32) * 80;

    float acc[4][4][4];
    #pragma unroll
    for (int i = 0; i < 4; i++)
        #pragma unroll
        for (int j = 0; j < 4; j++)
            #pragma unroll
            for (int q = 0; q < 4; q++) acc[i][j][q] = 0.f;

    const int S = K / 32;

    // prologue: fill stages 0..3 (4 groups in flight)
    #pragma unroll
    for (int s = 0; s < 4; s++)
        hfill(A, B, lda, ldb, s * 32, sbase, s, tid);

    int stage = 0;
    #pragma unroll 1
    for (int s = 0; s < S; s++) {
        // wait until group s complete: outstanding after wait = min(3, S-s-1)
        const int rem = S - 1 - s;
        if (rem >= 3)      asm volatile("cp.async.wait_group 3;" ::: "memory");
        else if (rem == 2) asm volatile("cp.async.wait_group 2;" ::: "memory");
        else if (rem == 1) asm volatile("cp.async.wait_group 1;" ::: "memory");
        else               asm volatile("cp.async.wait_group 0;" ::: "memory");
        __syncthreads();
        if (s + 4 < S) {
            int fstage = stage + 4; if (fstage >= NSTAGE) fstage -= NSTAGE;
            hfill(A, B, lda, ldb, (s + 4) * 32, sbase, fstage, tid);
        }

        const uint32_t sAb = sbase + stage * STAGE_B;
        const uint32_t sBb = sAb + 10240;

        #pragma unroll
        for (int kk = 0; kk < 2; kk++) {
            const uint32_t kadd = kk * 32;
            uint32_t af[4][4];
            #pragma unroll
            for (int mf = 0; mf < 4; mf++) {
                asm volatile("ldmatrix.sync.aligned.m8n8.x4.shared.b16 {%0,%1,%2,%3}, [%4];"
                    : "=r"(af[mf][0]), "=r"(af[mf][1]), "=r"(af[mf][2]), "=r"(af[mf][3])
                    : "r"(sAb + a_off + mf * 1280 + kadd));
            }
            uint32_t bf[4][2];
            #pragma unroll
            for (int p = 0; p < 2; p++) {
                asm volatile("ldmatrix.sync.aligned.m8n8.x4.shared.b16 {%0,%1,%2,%3}, [%4];"
                    : "=r"(bf[2*p][0]), "=r"(bf[2*p][1]), "=r"(bf[2*p+1][0]), "=r"(bf[2*p+1][1])
                    : "r"(sBb + b_off + p * 1280 + kadd));
            }
            #pragma unroll
            for (int mf = 0; mf < 4; mf++)
                #pragma unroll
                for (int nf = 0; nf < 4; nf++) {
                    asm volatile(
                        "mma.sync.aligned.m16n8k16.row.col.f32.f16.f16.f32 "
                        "{%0,%1,%2,%3}, {%4,%5,%6,%7}, {%8,%9}, {%0,%1,%2,%3};"
                        : "+f"(acc[mf][nf][0]), "+f"(acc[mf][nf][1]),
                          "+f"(acc[mf][nf][2]), "+f"(acc[mf][nf][3])
                        : "r"(af[mf][0]), "r"(af[mf][1]), "r"(af[mf][2]), "r"(af[mf][3]),
                          "r"(bf[nf][0]), "r"(bf[nf][1]));
                }
        }
        if (++stage >= NSTAGE) stage = 0;
    }

    const float* bp = bias ? bias + blockIdx.x * 128 : nullptr;
    #pragma unroll
    for (int mf = 0; mf < 4; mf++) {
        const int row = warpM * 64 + mf * 16 + g;
        #pragma unroll
        for (int nf = 0; nf < 4; nf++) {
            const int col = warpN * 32 + nf * 8 + 2 * t4;
            float b0 = 0.f, b1 = 0.f;
            if (bp) { b0 = bp[col]; b1 = bp[col + 1]; }
            float v00 = alpha * acc[mf][nf][0] + b0;
            float v01 = alpha * acc[mf][nf][1] + b1;
            float v10 = alpha * acc[mf][nf][2] + b0;
            float v11 = alpha * acc[mf][nf][3] + b1;
            if (HOUT) {
                __half* C = (__half*)Cv + blockIdx.z * sC
                          + (long long)blockIdx.y * 128 * ldc + blockIdx.x * 128;
                *(__half2*)(C + (long long)row * ldc + col)       = __floats2half2_rn(v00, v01);
                *(__half2*)(C + (long long)(row + 8) * ldc + col) = __floats2half2_rn(v10, v11);
            } else {
                float* C = (float*)Cv + blockIdx.z * sC
                         + (long long)blockIdx.y * 128 * ldc + blockIdx.x * 128;
                float2 u0 = { v00, v01 }, u1 = { v10, v11 };
                *(float2*)(C + (long long)row * ldc + col)       = u0;
                *(float2*)(C + (long long)(row + 8) * ldc + col) = u1;
            }
        }
    }
}

// ---------------- row softmax fp32 -> half P ----------------
__global__ void __launch_bounds__(256) softmax_kernel(const float* __restrict__ S,
                                                      __half* __restrict__ P) {
    const float* p = S + (size_t)blockIdx.x * NSP;
    __half2* o = (__half2*)(P + (size_t)blockIdx.x * NSP);
    float4 v[4];
    const int t = threadIdx.x;
    float m = -1e30f;
    #pragma unroll
    for (int i = 0; i < 4; i++) {
        v[i] = ((const float4*)p)[t + 256 * i];
        m = fmaxf(m, fmaxf(fmaxf(v[i].x, v[i].y), fmaxf(v[i].z, v[i].w)));
    }
    __shared__ float red[8];
    int w = t >> 5, l = t & 31;
    m = warpMax(m);
    if (l == 0) red[w] = m;
    __syncthreads();
    if (w == 0) {
        float tm = (l < 8) ? red[l] : -1e30f;
        tm = warpMax(tm);
        if (l == 0) red[0] = tm;
    }
    __syncthreads();
    m = red[0];
    __syncthreads();

    float s = 0.f;
    #pragma unroll
    for (int i = 0; i < 4; i++) {
        v[i].x = __expf(v[i].x - m);
        v[i].y = __expf(v[i].y - m);
        v[i].z = __expf(v[i].z - m);
        v[i].w = __expf(v[i].w - m);
        s += v[i].x + v[i].y + v[i].z + v[i].w;
    }
    s = warpSum(s);
    if (l == 0) red[w] = s;
    __syncthreads();
    if (w == 0) {
        float ts = (l < 8) ? red[l] : 0.f;
        ts = warpSum(ts);
        if (l == 0) red[0] = ts;
    }
    __syncthreads();
    float inv = __frcp_rn(red[0]);
    #pragma unroll
    for (int i = 0; i < 4; i++) {
        int base = (t + 256 * i) * 2;
        o[base]     = __floats2half2_rn(v[i].x * inv, v[i].y * inv);
        o[base + 1] = __floats2half2_rn(v[i].z * inv, v[i].w * inv);
    }
}

// ---------------- residual + transpose back ----------------
__global__ void residual_kernel(const float* __restrict__ x,
                                const float* __restrict__ proj,
                                float* __restrict__ out) {
    __shared__ float t[32][33];
    int n0 = blockIdx.x * 32, c0 = blockIdx.y * 32, b = blockIdx.z;
    int tx = threadIdx.x, ty = threadIdx.y;
    #pragma unroll
    for (int j = 0; j < 4; j++) {
        int n = n0 + ty + j * 8;
        t[ty + j * 8][tx] = proj[((size_t)(b * NSP + n)) * CH + c0 + tx];
    }
    __syncthreads();
    #pragma unroll
    for (int j = 0; j < 4; j++) {
        int c = c0 + ty + j * 8;
        size_t oi = ((size_t)(b * CH + c)) * NSP + n0 + tx;
        out[oi] = x[oi] + t[tx][ty + j * 8];
    }
}

// ---------------- launch ----------------
extern "C" void kernel_launch(void* const* d_in, const int* in_sizes, int n_in,
                              void* d_out, int out_size) {
    const float* x     = (const float*)d_in[0];
    const float* gw    = (const float*)d_in[1];
    const float* gb    = (const float*)d_in[2];
    const float* qkvW  = (const float*)d_in[3];
    const float* qkvB  = (const float*)d_in[4];
    const float* projW = (const float*)d_in[5];
    const float* projB = (const float*)d_in[6];
    float* out = (float*)d_out;

    __half *seqh, *qkvh, *ph, *vth, *attnh, *qkvWh, *projWh;
    float *scor, *proj, *stats;
    cudaGetSymbolAddress((void**)&seqh,  g_seqh);
    cudaGetSymbolAddress((void**)&qkvh,  g_qkvh);
    cudaGetSymbolAddress((void**)&ph,    g_ph);
    cudaGetSymbolAddress((void**)&vth,   g_vth);
    cudaGetSymbolAddress((void**)&attnh, g_attnh);
    cudaGetSymbolAddress((void**)&qkvWh, g_qkvWh);
    cudaGetSymbolAddress((void**)&projWh,g_projWh);
    cudaGetSymbolAddress((void**)&scor,  g_scor);
    cudaGetSymbolAddress((void**)&proj,  g_proj);
    cudaGetSymbolAddress((void**)&stats, g_stats);

    static bool attr_done = false;
    if (!attr_done) {
        cudaFuncSetAttribute((const void*)hgemm<true>,
                             cudaFuncAttributeMaxDynamicSharedMemorySize, HG_SMEM);
        cudaFuncSetAttribute((const void*)hgemm<false>,
                             cudaFuncAttributeMaxDynamicSharedMemorySize, HG_SMEM);
        attr_done = true;
    }

    // 1. GroupNorm + weight conversion
    gn_stats_kernel<<<BATCH * NGRP, 256>>>(x, stats);
    wconv_kernel<<<C3 * CH / 1024, 256>>>(qkvW, projW, qkvWh, projWh);
    gn_apply_kernel<<<dim3(NSP / 32, CH / 32, BATCH), dim3(32, 8)>>>(x, stats, gw, gb, seqh);

    // 2. QKV projection
    hgemm<true><<<dim3(C3 / 128, (BATCH * NSP) / 128, 1), 256, HG_SMEM>>>(
        seqh, CH, 0, qkvWh, CH, 0, qkvh, C3, 0, CH, 1.f, qkvB);

    // 3. V transpose
    vtrans_kernel<<<dim3(NSP / 32, CH / 32, BATCH), dim3(32, 8)>>>(qkvh, vth);

    // 4. Scores: Q K^T * scale -> fp32
    const float scale = 0.044194173824159216f;
    hgemm<false><<<dim3(NSP / 128, NSP / 128, BATCH), 256, HG_SMEM>>>(
        qkvh, C3, (long long)NSP * C3,
        qkvh + CH, C3, (long long)NSP * C3,
        scor, NSP, (long long)NSP * NSP,
        CH, scale, nullptr);

    // 5. Softmax -> half P
    softmax_kernel<<<BATCH * NSP, 256>>>(scor, ph);

    // 6. O = P V^T
    hgemm<true><<<dim3(CH / 128, NSP / 128, BATCH), 256, HG_SMEM>>>(
        ph, NSP, (long long)NSP * NSP,
        vth, NSP, (long long)CH * NSP,
        attnh, CH, (long long)NSP * CH,
        NSP, 1.f, nullptr);

    // 7. Output projection -> fp32
    hgemm<false><<<dim3(CH / 128, (BATCH * NSP) / 128, 1), 256, HG_SMEM>>>(
        attnh, CH, 0, projWh, CH, 0, proj, CH, 0, CH, 1.f, projB);

    // 8. Residual + transpose back
    residual_kernel<<<dim3(NSP / 32, CH / 32, BATCH), dim3(32, 8)>>>(x, proj, out);
}